// round 8
// baseline (speedup 1.0000x reference)
#include <cuda_runtime.h>
#include <cuda_bf16.h>
#include <cstdint>

#define S 4096
#define HH 64
#define WW 64

// ---------------- scratch (no allocations allowed) ----------------
__device__ float g_hqkv[4 * 96 * S];
__device__ float g_mkv [4 * 64 * S];
__device__ float g_Z2  [4 * 64 * S];
__device__ float g_Zp  [4 * 32 * S];
__device__ float g_conv[4 * 192 * S];

// ---------------- mma.sync helpers ----------------
__device__ __forceinline__ void mma16816(float* c, const uint32_t* a, uint32_t b0, uint32_t b1) {
    asm volatile(
        "mma.sync.aligned.m16n8k16.row.col.f32.bf16.bf16.f32 "
        "{%0,%1,%2,%3}, {%4,%5,%6,%7}, {%8,%9}, {%0,%1,%2,%3};"
        : "+f"(c[0]), "+f"(c[1]), "+f"(c[2]), "+f"(c[3])
        : "r"(a[0]), "r"(a[1]), "r"(a[2]), "r"(a[3]), "r"(b0), "r"(b1));
}
__device__ __forceinline__ void mma1688t(float* c, const uint32_t* a, uint32_t b0, uint32_t b1) {
    asm volatile(
        "mma.sync.aligned.m16n8k8.row.col.f32.tf32.tf32.f32 "
        "{%0,%1,%2,%3}, {%4,%5,%6,%7}, {%8,%9}, {%0,%1,%2,%3};"
        : "+f"(c[0]), "+f"(c[1]), "+f"(c[2]), "+f"(c[3])
        : "r"(a[0]), "r"(a[1]), "r"(a[2]), "r"(a[3]), "r"(b0), "r"(b1));
}
__device__ __forceinline__ uint32_t packbf(float lo, float hi) {
    uint32_t r;
    asm("cvt.rn.bf16x2.f32 %0, %2, %1;" : "=r"(r) : "f"(lo), "f"(hi));
    return r;
}
__device__ __forceinline__ uint32_t f2tf32(float f) {
    uint32_t r;
    asm("cvt.rna.tf32.f32 %0, %1;" : "=r"(r) : "f"(f));
    return r;
}

// ---------------- 1x1 projection as tf32 GEMM (unchanged) ----------------
#define PRJ_XS_ST 136
#define PRJ_WS_ST 40

__device__ __forceinline__ void proj_gemm_body(
    uint32_t* Xs, uint32_t* Ws2,
    const float* Xg, const float* Wg, const float* bg,
    float* outg, int s0)
{
    int tid = threadIdx.x;
    int w = tid >> 5, lane = tid & 31;
    int lq = lane >> 2, l4 = lane & 3;

    for (int i = tid; i < 64 * 128; i += 128) {
        int ci = i >> 7, sl = i & 127;
        Xs[ci * PRJ_XS_ST + sl] = f2tf32(Xg[(size_t)ci * S + s0 + sl]);
    }
    for (int i = tid; i < 32 * 64; i += 128) {
        int co = i >> 6, ci = i & 63;
        Ws2[ci * PRJ_WS_ST + co] = f2tf32(Wg[co * 64 + ci]);
    }
    __syncthreads();

    float oacc[2][4][4];
#pragma unroll
    for (int mt = 0; mt < 2; mt++)
#pragma unroll
        for (int nt = 0; nt < 4; nt++)
#pragma unroll
            for (int r = 0; r < 4; r++) oacc[mt][nt][r] = 0.f;

#pragma unroll
    for (int kb8 = 0; kb8 < 8; kb8++) {
        int kb = kb8 * 8;
        uint32_t a[2][4];
#pragma unroll
        for (int mt = 0; mt < 2; mt++) {
            int co0 = mt * 16 + lq;
            a[mt][0] = Ws2[(kb + l4) * PRJ_WS_ST + co0];
            a[mt][1] = Ws2[(kb + l4) * PRJ_WS_ST + co0 + 8];
            a[mt][2] = Ws2[(kb + l4 + 4) * PRJ_WS_ST + co0];
            a[mt][3] = Ws2[(kb + l4 + 4) * PRJ_WS_ST + co0 + 8];
        }
#pragma unroll
        for (int nt = 0; nt < 4; nt++) {
            int scol = w * 32 + nt * 8 + lq;
            uint32_t b0 = Xs[(kb + l4) * PRJ_XS_ST + scol];
            uint32_t b1 = Xs[(kb + l4 + 4) * PRJ_XS_ST + scol];
            mma1688t(oacc[0][nt], a[0], b0, b1);
            mma1688t(oacc[1][nt], a[1], b0, b1);
        }
    }

#pragma unroll
    for (int mt = 0; mt < 2; mt++) {
        int coA = mt * 16 + lq, coB = coA + 8;
        float bA = bg[coA], bB = bg[coB];
#pragma unroll
        for (int nt = 0; nt < 4; nt++) {
            int x = s0 + w * 32 + nt * 8 + 2 * l4;
            *(float2*)&outg[(size_t)coA * S + x] = make_float2(oacc[mt][nt][0] + bA, oacc[mt][nt][1] + bA);
            *(float2*)&outg[(size_t)coB * S + x] = make_float2(oacc[mt][nt][2] + bB, oacc[mt][nt][3] + bB);
        }
    }
}

__global__ __launch_bounds__(128)
void projhm_kernel(const float* __restrict__ h, const float* __restrict__ Wh,
                   const float* __restrict__ bh, float* __restrict__ hqkv,
                   const float* __restrict__ m, const float* __restrict__ Wm,
                   const float* __restrict__ bm, float* __restrict__ mkv) {
    __shared__ uint32_t Xs[64 * PRJ_XS_ST];
    __shared__ uint32_t Ws2[64 * PRJ_WS_ST];
    int n = blockIdx.z, y = blockIdx.y;
    int s0 = blockIdx.x * 128;
    if (y < 3) {
        int co0 = y * 32;
        proj_gemm_body(Xs, Ws2, h + (size_t)n * 64 * S, Wh + (size_t)co0 * 64, bh + co0,
                       hqkv + ((size_t)n * 96 + co0) * S, s0);
    } else {
        int co0 = (y - 3) * 32;
        proj_gemm_body(Xs, Ws2, m + (size_t)n * 64 * S, Wm + (size_t)co0 * 64, bm + co0,
                       mkv + ((size_t)n * 64 + co0) * S, s0);
    }
}

__global__ __launch_bounds__(128)
void projz_kernel(const float* __restrict__ Z2, const float* __restrict__ Wz,
                  const float* __restrict__ bz, float* __restrict__ Zp) {
    __shared__ uint32_t Xs[64 * PRJ_XS_ST];
    __shared__ uint32_t Ws2[64 * PRJ_WS_ST];
    int n = blockIdx.z;
    int s0 = blockIdx.x * 128;
    proj_gemm_body(Xs, Ws2, Z2 + (size_t)n * 64 * S, Wz, bz, Zp + (size_t)n * 32 * S, s0);
}

// ---------------- flash attention: 256 queries/CTA, 8 warps, double-buffered ----------------
// grid (16 qtiles, 2 att, 4 n), 256 threads. Warp w owns query rows 32w..32w+31.
// smem words: Qs 256x20 = 5120 | Kbuf[2] 64x20 = 1280 ea | Vbuf[2] 32x35 = 1120 ea
#define AQ_W   5120
#define AK_W   1280
#define AV_W   1120
#define A_TOT  (AQ_W + 2 * AK_W + 2 * AV_W)

__global__ __launch_bounds__(256)
void attn_mma_kernel(const float* __restrict__ hqkv, const float* __restrict__ mkv,
                     float* __restrict__ Z2) {
    __shared__ uint32_t smw[A_TOT];
    uint32_t* Qsw = smw;
    uint32_t* Kb0 = smw + AQ_W;
    uint32_t* Vb0 = smw + AQ_W + 2 * AK_W;
    __nv_bfloat16* Qh = (__nv_bfloat16*)Qsw;

    int tid = threadIdx.x;
    int w = tid >> 5, lane = tid & 31;
    int lq = lane >> 2, lj = lane & 3;
    int n = blockIdx.z, att = blockIdx.y;
    int q0 = blockIdx.x * 256;

    const float* Q = hqkv + (size_t)n * 96 * S;
    const float* K = (att == 0) ? hqkv + ((size_t)n * 96 + 32) * S
                                : mkv  + ((size_t)n * 64 +  0) * S;
    const float* V = (att == 0) ? hqkv + ((size_t)n * 96 + 64) * S
                                : mkv  + ((size_t)n * 64 + 32) * S;
    float* Out = Z2 + ((size_t)n * 64 + att * 32) * S;

    const float scale = 0.17677669529663687f;
    for (int i = tid; i < 8192; i += 256) {
        int d = i >> 8, q = i & 255;
        Qh[q * 40 + d] = __float2bfloat16(Q[(size_t)d * S + q0 + q] * scale);
    }
    __syncthreads();

    uint32_t qa[2][2][4];
#pragma unroll
    for (int mt = 0; mt < 2; mt++) {
        int r0 = 32 * w + 16 * mt + lq;
#pragma unroll
        for (int ks = 0; ks < 2; ks++) {
            qa[mt][ks][0] = Qsw[r0 * 20 + ks * 8 + lj];
            qa[mt][ks][1] = Qsw[(r0 + 8) * 20 + ks * 8 + lj];
            qa[mt][ks][2] = Qsw[r0 * 20 + ks * 8 + lj + 4];
            qa[mt][ks][3] = Qsw[(r0 + 8) * 20 + ks * 8 + lj + 4];
        }
    }

    float oacc[2][4][4];
#pragma unroll
    for (int mt = 0; mt < 2; mt++)
#pragma unroll
        for (int nt = 0; nt < 4; nt++)
#pragma unroll
            for (int r = 0; r < 4; r++) oacc[mt][nt][r] = 0.f;
    float l_acc[4] = {0.f, 0.f, 0.f, 0.f};

    // ---- prefetch chunk 0
    uint32_t kreg[4], vreg[4];
#pragma unroll
    for (int j = 0; j < 4; j++) {
        int idx = j * 256 + tid;
        int k = idx & 63, dp = idx >> 6;
        kreg[j] = packbf(K[(size_t)(2 * dp) * S + k], K[(size_t)(2 * dp + 1) * S + k]);
    }
#pragma unroll
    for (int j = 0; j < 4; j++) {
        int idx = j * 256 + tid;
        int d = idx >> 5, kp = idx & 31;
        float2 v2 = *(const float2*)&V[(size_t)d * S + 2 * kp];
        vreg[j] = packbf(v2.x, v2.y);
    }

#pragma unroll 1
    for (int kt = 0; kt < 64; kt++) {
        uint32_t* Kbuf = Kb0 + (kt & 1) * AK_W;
        uint32_t* Vbuf = Vb0 + (kt & 1) * AV_W;
#pragma unroll
        for (int j = 0; j < 4; j++) {
            int idx = j * 256 + tid;
            Kbuf[(idx & 63) * 20 + (idx >> 6)] = kreg[j];
        }
#pragma unroll
        for (int j = 0; j < 4; j++) {
            int idx = j * 256 + tid;
            Vbuf[(idx >> 5) * 35 + (idx & 31)] = vreg[j];
        }
        __syncthreads();

        if (kt < 63) {
            int kb = (kt + 1) * 64;
#pragma unroll
            for (int j = 0; j < 4; j++) {
                int idx = j * 256 + tid;
                int k = idx & 63, dp = idx >> 6;
                kreg[j] = packbf(K[(size_t)(2 * dp) * S + kb + k], K[(size_t)(2 * dp + 1) * S + kb + k]);
            }
#pragma unroll
            for (int j = 0; j < 4; j++) {
                int idx = j * 256 + tid;
                int d = idx >> 5, kp = idx & 31;
                float2 v2 = *(const float2*)&V[(size_t)d * S + kb + 2 * kp];
                vreg[j] = packbf(v2.x, v2.y);
            }
        }

        // ---- QK + softmax + pack P
        uint32_t p[2][4][4];
        float rs[2][2] = {{0.f, 0.f}, {0.f, 0.f}};
#pragma unroll
        for (int nn = 0; nn < 8; nn++) {
            float c[2][4];
#pragma unroll
            for (int mt = 0; mt < 2; mt++)
#pragma unroll
                for (int r = 0; r < 4; r++) c[mt][r] = 0.f;
#pragma unroll
            for (int ks = 0; ks < 2; ks++) {
                int bw = (nn * 8 + lq) * 20 + ks * 8 + lj;
                uint32_t b0 = Kbuf[bw], b1 = Kbuf[bw + 4];
                mma16816(c[0], qa[0][ks], b0, b1);
                mma16816(c[1], qa[1][ks], b0, b1);
            }
            int kk = nn >> 1, half = (nn & 1) * 2;
#pragma unroll
            for (int mt = 0; mt < 2; mt++) {
                float e0 = __expf(c[mt][0]), e1 = __expf(c[mt][1]);
                float e2 = __expf(c[mt][2]), e3 = __expf(c[mt][3]);
                rs[mt][0] += e0 + e1; rs[mt][1] += e2 + e3;
                p[mt][kk][half + 0] = packbf(e0, e1);
                p[mt][kk][half + 1] = packbf(e2, e3);
            }
        }
#pragma unroll
        for (int mt = 0; mt < 2; mt++) {
            float r0 = rs[mt][0], r1 = rs[mt][1];
            r0 += __shfl_xor_sync(0xffffffffu, r0, 1);
            r0 += __shfl_xor_sync(0xffffffffu, r0, 2);
            r1 += __shfl_xor_sync(0xffffffffu, r1, 1);
            r1 += __shfl_xor_sync(0xffffffffu, r1, 2);
            l_acc[mt * 2 + 0] += r0;
            l_acc[mt * 2 + 1] += r1;
        }

        // ---- O += P @ V
#pragma unroll
        for (int nt = 0; nt < 4; nt++) {
#pragma unroll
            for (int kk = 0; kk < 4; kk++) {
                int bw = (nt * 8 + lq) * 35 + kk * 8 + lj;
                uint32_t b0 = Vbuf[bw], b1 = Vbuf[bw + 4];
                mma16816(oacc[0][nt], p[0][kk], b0, b1);
                mma16816(oacc[1][nt], p[1][kk], b0, b1);
            }
        }
    }

    // ---- epilogue: normalize, stage Osm[d][q] stride 258, coalesced store
    __syncthreads();
    float* Osm = (float*)smw;
    float inv[4];
#pragma unroll
    for (int r = 0; r < 4; r++) inv[r] = 1.0f / l_acc[r];
#pragma unroll
    for (int mt = 0; mt < 2; mt++) {
        int r0 = 32 * w + 16 * mt + lq;
#pragma unroll
        for (int nt = 0; nt < 4; nt++) {
            int d0 = nt * 8 + 2 * lj;
            Osm[(d0 + 0) * 258 + r0]     = oacc[mt][nt][0] * inv[mt * 2];
            Osm[(d0 + 1) * 258 + r0]     = oacc[mt][nt][1] * inv[mt * 2];
            Osm[(d0 + 0) * 258 + r0 + 8] = oacc[mt][nt][2] * inv[mt * 2 + 1];
            Osm[(d0 + 1) * 258 + r0 + 8] = oacc[mt][nt][3] * inv[mt * 2 + 1];
        }
    }
    __syncthreads();
    for (int i = tid; i < 8192; i += 256) {
        int d = i >> 8, q = i & 255;
        Out[(size_t)d * S + q0 + q] = Osm[d * 258 + q];
    }
}

// ---------------- 3x3 conv implicit GEMM: fragment-major weights, unrolled ----------------
// grid (16 tiles, 6 cog, 4 n), 256 threads (8 warps). M=32 co, N=256 px, K=864.
// patchF: 16 ci x 332 words. Wfrag[chunk(18)][mt(2)][lane(32)] = uint4 A-fragment.
__global__ __launch_bounds__(256)
void conv_tc_kernel(const float* __restrict__ Zin, const float* __restrict__ hin,
                    const float* __restrict__ Wo, const float* __restrict__ bo,
                    float* __restrict__ out) {
    __shared__ uint32_t patchF[16 * 332];
    __shared__ uint4 Wfrag[18 * 2 * 32];

    int tid = threadIdx.x;
    int w = tid >> 5, lane = tid & 31;
    int lq = lane >> 2, l4 = lane & 3;
    int n = blockIdx.z, cog = blockIdx.y, tile = blockIdx.x;
    int ty0 = (tile >> 2) * 16, tx0 = (tile & 3) * 16;

    // precomputed staging coordinates (2 positions/thread, 1 div each)
    int pos0 = tid;
    int yy0 = pos0 / 18 + ty0 - 1, xx0 = pos0 % 18 + tx0 - 1;
    bool va0 = (yy0 >= 0 && yy0 < HH && xx0 >= 0 && xx0 < WW);
    int g0 = yy0 * WW + xx0;
    int pos1 = tid + 256;
    bool has1 = pos1 < 324;
    int yy1 = pos1 / 18 + ty0 - 1, xx1 = pos1 % 18 + tx0 - 1;
    bool va1 = has1 && (yy1 >= 0 && yy1 < HH && xx1 >= 0 && xx1 < WW);
    int g1 = yy1 * WW + xx1;

    // B-operand row pointers + per-nt pixel bases (all loop-invariant)
    const uint32_t* rowA = patchF + l4 * 332;
    const uint32_t* rowB = patchF + (8 + l4) * 332;
    int bbase[4];
#pragma unroll
    for (int nt = 0; nt < 4; nt++)
        bbase[nt] = (2 * w + (nt >> 1)) * 18 + (nt & 1) * 8 + lq;

    float oacc[2][4][4];
#pragma unroll
    for (int mt = 0; mt < 2; mt++)
#pragma unroll
        for (int nt = 0; nt < 4; nt++)
#pragma unroll
            for (int r = 0; r < 4; r++) oacc[mt][nt][r] = 0.f;

#pragma unroll 1
    for (int cig = 0; cig < 6; cig++) {
        const float* base = (cig < 2)
            ? Zin + ((size_t)n * 32 + cig * 16) * S
            : hin + ((size_t)n * 64 + (cig * 16 - 32)) * S;
        __syncthreads();
        // stage patch: thread covers its 2 fixed positions across all 16 ci
#pragma unroll
        for (int ci = 0; ci < 16; ci++)
            patchF[ci * 332 + pos0] = va0 ? f2tf32(base[(size_t)ci * S + g0]) : 0u;
        if (has1) {
#pragma unroll
            for (int ci = 0; ci < 16; ci++)
                patchF[ci * 332 + pos1] = va1 ? f2tf32(base[(size_t)ci * S + g1]) : 0u;
        }
        // stage weights in fragment-major order
        for (int i = tid; i < 1152; i += 256) {
            int ln = i & 31, mtc = i >> 5;
            int mt = mtc & 1, chunk = mtc >> 1;
            int khkw = chunk >> 1, c8 = chunk & 1;
            int ciL = c8 * 8 + (ln & 3);
            int co0 = mt * 16 + (ln >> 2);
            const float* wp = Wo + (((size_t)cog * 32 + co0) * 96 + cig * 16 + ciL) * 9 + khkw;
            Wfrag[i] = make_uint4(f2tf32(wp[0]), f2tf32(wp[8 * 864]),
                                  f2tf32(wp[36]), f2tf32(wp[8 * 864 + 36]));
        }
        __syncthreads();

#pragma unroll
        for (int khkw = 0; khkw < 9; khkw++) {
            int kh = khkw / 3, kw = khkw % 3;     // constants after unroll
#pragma unroll
            for (int c8 = 0; c8 < 2; c8++) {
                int chunk = khkw * 2 + c8;
                uint4 a0 = Wfrag[(chunk * 2 + 0) * 32 + lane];
                uint4 a1 = Wfrag[(chunk * 2 + 1) * 32 + lane];
                const uint32_t* rr = c8 ? rowB : rowA;
#pragma unroll
                for (int nt = 0; nt < 4; nt++) {
                    int off = bbase[nt] + kh * 18 + kw;
                    uint32_t b0 = rr[off];
                    uint32_t b1 = rr[4 * 332 + off];
                    mma1688t(oacc[0][nt], (const uint32_t*)&a0, b0, b1);
                    mma1688t(oacc[1][nt], (const uint32_t*)&a1, b0, b1);
                }
            }
        }
    }

#pragma unroll
    for (int mt = 0; mt < 2; mt++) {
        int coA = cog * 32 + mt * 16 + lq;
        int coB = coA + 8;
        float bA = bo[coA], bB = bo[coB];
        size_t baseA = ((size_t)n * 192 + coA) * S;
        size_t baseB = ((size_t)n * 192 + coB) * S;
#pragma unroll
        for (int nt = 0; nt < 4; nt++) {
            int y = ty0 + 2 * w + (nt >> 1);
            int x = tx0 + (nt & 1) * 8 + 2 * l4;
            *(float2*)&out[baseA + y * WW + x] = make_float2(oacc[mt][nt][0] + bA, oacc[mt][nt][1] + bA);
            *(float2*)&out[baseB + y * WW + x] = make_float2(oacc[mt][nt][2] + bB, oacc[mt][nt][3] + bB);
        }
    }
}

// ---------------- gates (float4) ----------------
__global__ __launch_bounds__(256)
void gates_kernel(const float* __restrict__ conv, const float* __restrict__ m,
                  float* __restrict__ out) {
    int idx4 = blockIdx.x * 256 + threadIdx.x;
    int n = idx4 >> 16;
    int rem = (idx4 & 65535) * 4;
    size_t base = (size_t)n * 192 * S;
    float4 iv = *(const float4*)&conv[base + rem];
    float4 gv = *(const float4*)&conv[base + 64 * S + rem];
    float4 ov = *(const float4*)&conv[base + 128 * S + rem];
    float4 mi = *(const float4*)&m[(size_t)n * 64 * S + rem];
    float4 hn, mn;
    {
        float si = 1.0f / (1.0f + __expf(-iv.x)), gg = tanhf(gv.x), so = 1.0f / (1.0f + __expf(-ov.x));
        mn.x = si * gg + (1.0f - si) * mi.x; hn.x = so * mn.x;
        si = 1.0f / (1.0f + __expf(-iv.y)); gg = tanhf(gv.y); so = 1.0f / (1.0f + __expf(-ov.y));
        mn.y = si * gg + (1.0f - si) * mi.y; hn.y = so * mn.y;
        si = 1.0f / (1.0f + __expf(-iv.z)); gg = tanhf(gv.z); so = 1.0f / (1.0f + __expf(-ov.z));
        mn.z = si * gg + (1.0f - si) * mi.z; hn.z = so * mn.z;
        si = 1.0f / (1.0f + __expf(-iv.w)); gg = tanhf(gv.w); so = 1.0f / (1.0f + __expf(-ov.w));
        mn.w = si * gg + (1.0f - si) * mi.w; hn.w = so * mn.w;
    }
    size_t oidx = (size_t)n * 64 * S + rem;
    *(float4*)&out[oidx] = hn;
    *(float4*)&out[1048576 + oidx] = mn;
}

// ---------------- launch ----------------
extern "C" void kernel_launch(void* const* d_in, const int* in_sizes, int n_in,
                              void* d_out, int out_size) {
    const float* h  = (const float*)d_in[0];
    const float* m  = (const float*)d_in[1];
    const float* Wh = (const float*)d_in[2];
    const float* bh = (const float*)d_in[3];
    const float* Wm = (const float*)d_in[4];
    const float* bm = (const float*)d_in[5];
    const float* Wz = (const float*)d_in[6];
    const float* bz = (const float*)d_in[7];
    const float* Wo = (const float*)d_in[8];
    const float* bo = (const float*)d_in[9];
    float* out = (float*)d_out;

    float *pHqkv, *pMkv, *pZ2, *pZp, *pConv;
    cudaGetSymbolAddress((void**)&pHqkv, g_hqkv);
    cudaGetSymbolAddress((void**)&pMkv,  g_mkv);
    cudaGetSymbolAddress((void**)&pZ2,   g_Z2);
    cudaGetSymbolAddress((void**)&pZp,   g_Zp);
    cudaGetSymbolAddress((void**)&pConv, g_conv);

    projhm_kernel<<<dim3(32, 5, 4), 128>>>(h, Wh, bh, pHqkv, m, Wm, bm, pMkv);
    attn_mma_kernel<<<dim3(16, 2, 4), 256>>>(pHqkv, pMkv, pZ2);
    projz_kernel<<<dim3(32, 1, 4), 128>>>(pZ2, Wz, bz, pZp);
    conv_tc_kernel<<<dim3(16, 6, 4), 256>>>(pZp, h, Wo, bo, pConv);
    gates_kernel<<<1024, 256>>>(pConv, m, out);
}

// round 10
// speedup vs baseline: 1.6134x; 1.6134x over previous
#include <cuda_runtime.h>
#include <cuda_bf16.h>
#include <cuda_fp16.h>
#include <cstdint>

#define S 4096
#define HH 64
#define WW 64

// ---------------- scratch (no allocations allowed) ----------------
__device__ float g_hqkv[4 * 96 * S];
__device__ float g_mkv [4 * 64 * S];
__device__ float g_Z2  [4 * 64 * S];
__device__ float g_Zp  [4 * 32 * S];
__device__ float g_conv[4 * 192 * S];

// ---------------- mma.sync helpers ----------------
__device__ __forceinline__ void mma16816(float* c, const uint32_t* a, uint32_t b0, uint32_t b1) {
    asm volatile(
        "mma.sync.aligned.m16n8k16.row.col.f32.bf16.bf16.f32 "
        "{%0,%1,%2,%3}, {%4,%5,%6,%7}, {%8,%9}, {%0,%1,%2,%3};"
        : "+f"(c[0]), "+f"(c[1]), "+f"(c[2]), "+f"(c[3])
        : "r"(a[0]), "r"(a[1]), "r"(a[2]), "r"(a[3]), "r"(b0), "r"(b1));
}
__device__ __forceinline__ void mma16816h(float* c, const uint32_t* a, uint32_t b0, uint32_t b1) {
    asm volatile(
        "mma.sync.aligned.m16n8k16.row.col.f32.f16.f16.f32 "
        "{%0,%1,%2,%3}, {%4,%5,%6,%7}, {%8,%9}, {%0,%1,%2,%3};"
        : "+f"(c[0]), "+f"(c[1]), "+f"(c[2]), "+f"(c[3])
        : "r"(a[0]), "r"(a[1]), "r"(a[2]), "r"(a[3]), "r"(b0), "r"(b1));
}
__device__ __forceinline__ void mma1688t(float* c, const uint32_t* a, uint32_t b0, uint32_t b1) {
    asm volatile(
        "mma.sync.aligned.m16n8k8.row.col.f32.tf32.tf32.f32 "
        "{%0,%1,%2,%3}, {%4,%5,%6,%7}, {%8,%9}, {%0,%1,%2,%3};"
        : "+f"(c[0]), "+f"(c[1]), "+f"(c[2]), "+f"(c[3])
        : "r"(a[0]), "r"(a[1]), "r"(a[2]), "r"(a[3]), "r"(b0), "r"(b1));
}
__device__ __forceinline__ uint32_t packbf(float lo, float hi) {
    uint32_t r;
    asm("cvt.rn.bf16x2.f32 %0, %2, %1;" : "=r"(r) : "f"(lo), "f"(hi));
    return r;
}
__device__ __forceinline__ uint32_t packh(float lo, float hi) {
    uint32_t r;
    asm("cvt.rn.f16x2.f32 %0, %2, %1;" : "=r"(r) : "f"(lo), "f"(hi));
    return r;
}
__device__ __forceinline__ uint32_t h2ex2(uint32_t x) {
    uint32_t r;
    asm("ex2.approx.f16x2 %0, %1;" : "=r"(r) : "r"(x));
    return r;
}
__device__ __forceinline__ uint32_t hadd2u(uint32_t a, uint32_t b) {
    uint32_t r;
    asm("add.rn.f16x2 %0, %1, %2;" : "=r"(r) : "r"(a), "r"(b));
    return r;
}
__device__ __forceinline__ uint32_t f2tf32(float f) {
    uint32_t r;
    asm("cvt.rna.tf32.f32 %0, %1;" : "=r"(r) : "f"(f));
    return r;
}

// ---------------- 1x1 projection as tf32 GEMM (unchanged) ----------------
#define PRJ_XS_ST 136
#define PRJ_WS_ST 40

__device__ __forceinline__ void proj_gemm_body(
    uint32_t* Xs, uint32_t* Ws2,
    const float* Xg, const float* Wg, const float* bg,
    float* outg, int s0)
{
    int tid = threadIdx.x;
    int w = tid >> 5, lane = tid & 31;
    int lq = lane >> 2, l4 = lane & 3;

    for (int i = tid; i < 64 * 128; i += 128) {
        int ci = i >> 7, sl = i & 127;
        Xs[ci * PRJ_XS_ST + sl] = f2tf32(Xg[(size_t)ci * S + s0 + sl]);
    }
    for (int i = tid; i < 32 * 64; i += 128) {
        int co = i >> 6, ci = i & 63;
        Ws2[ci * PRJ_WS_ST + co] = f2tf32(Wg[co * 64 + ci]);
    }
    __syncthreads();

    float oacc[2][4][4];
#pragma unroll
    for (int mt = 0; mt < 2; mt++)
#pragma unroll
        for (int nt = 0; nt < 4; nt++)
#pragma unroll
            for (int r = 0; r < 4; r++) oacc[mt][nt][r] = 0.f;

#pragma unroll
    for (int kb8 = 0; kb8 < 8; kb8++) {
        int kb = kb8 * 8;
        uint32_t a[2][4];
#pragma unroll
        for (int mt = 0; mt < 2; mt++) {
            int co0 = mt * 16 + lq;
            a[mt][0] = Ws2[(kb + l4) * PRJ_WS_ST + co0];
            a[mt][1] = Ws2[(kb + l4) * PRJ_WS_ST + co0 + 8];
            a[mt][2] = Ws2[(kb + l4 + 4) * PRJ_WS_ST + co0];
            a[mt][3] = Ws2[(kb + l4 + 4) * PRJ_WS_ST + co0 + 8];
        }
#pragma unroll
        for (int nt = 0; nt < 4; nt++) {
            int scol = w * 32 + nt * 8 + lq;
            uint32_t b0 = Xs[(kb + l4) * PRJ_XS_ST + scol];
            uint32_t b1 = Xs[(kb + l4 + 4) * PRJ_XS_ST + scol];
            mma1688t(oacc[0][nt], a[0], b0, b1);
            mma1688t(oacc[1][nt], a[1], b0, b1);
        }
    }

#pragma unroll
    for (int mt = 0; mt < 2; mt++) {
        int coA = mt * 16 + lq, coB = coA + 8;
        float bA = bg[coA], bB = bg[coB];
#pragma unroll
        for (int nt = 0; nt < 4; nt++) {
            int x = s0 + w * 32 + nt * 8 + 2 * l4;
            *(float2*)&outg[(size_t)coA * S + x] = make_float2(oacc[mt][nt][0] + bA, oacc[mt][nt][1] + bA);
            *(float2*)&outg[(size_t)coB * S + x] = make_float2(oacc[mt][nt][2] + bB, oacc[mt][nt][3] + bB);
        }
    }
}

__global__ __launch_bounds__(128)
void projhm_kernel(const float* __restrict__ h, const float* __restrict__ Wh,
                   const float* __restrict__ bh, float* __restrict__ hqkv,
                   const float* __restrict__ m, const float* __restrict__ Wm,
                   const float* __restrict__ bm, float* __restrict__ mkv) {
    __shared__ uint32_t Xs[64 * PRJ_XS_ST];
    __shared__ uint32_t Ws2[64 * PRJ_WS_ST];
    int n = blockIdx.z, y = blockIdx.y;
    int s0 = blockIdx.x * 128;
    if (y < 3) {
        int co0 = y * 32;
        proj_gemm_body(Xs, Ws2, h + (size_t)n * 64 * S, Wh + (size_t)co0 * 64, bh + co0,
                       hqkv + ((size_t)n * 96 + co0) * S, s0);
    } else {
        int co0 = (y - 3) * 32;
        proj_gemm_body(Xs, Ws2, m + (size_t)n * 64 * S, Wm + (size_t)co0 * 64, bm + co0,
                       mkv + ((size_t)n * 64 + co0) * S, s0);
    }
}

__global__ __launch_bounds__(128)
void projz_kernel(const float* __restrict__ Z2, const float* __restrict__ Wz,
                  const float* __restrict__ bz, float* __restrict__ Zp) {
    __shared__ uint32_t Xs[64 * PRJ_XS_ST];
    __shared__ uint32_t Ws2[64 * PRJ_WS_ST];
    int n = blockIdx.z;
    int s0 = blockIdx.x * 128;
    proj_gemm_body(Xs, Ws2, Z2 + (size_t)n * 64 * S, Wz, bz, Zp + (size_t)n * 32 * S, s0);
}

// ---------------- flash attention: 128 thr / 256 CTAs, f16x2 exp, f16 PV ----------------
// Q pre-scaled by log2(e)/sqrt(32) => scores are base-2 exponents; P = ex2(score).
// smem words: Qs 128x20 = 2560 | Kbuf[2] 64x20 = 1280 ea | Vbuf[2] 32x35 = 1120 ea
#define AQ_W   2560
#define AK_W   1280
#define AV_W   1120
#define A_TOT  (AQ_W + 2 * AK_W + 2 * AV_W)

__global__ __launch_bounds__(128)
void attn_mma_kernel(const float* __restrict__ hqkv, const float* __restrict__ mkv,
                     float* __restrict__ Z2) {
    __shared__ uint32_t smw[A_TOT];
    uint32_t* Qsw = smw;
    uint32_t* Kb0 = smw + AQ_W;
    uint32_t* Vb0 = smw + AQ_W + 2 * AK_W;
    __nv_bfloat16* Qh = (__nv_bfloat16*)Qsw;

    int tid = threadIdx.x;
    int w = tid >> 5, lane = tid & 31;
    int lq = lane >> 2, lj = lane & 3;
    int n = blockIdx.z, att = blockIdx.y;
    int q0 = blockIdx.x * 128;

    const float* Q = hqkv + (size_t)n * 96 * S;
    const float* K = (att == 0) ? hqkv + ((size_t)n * 96 + 32) * S
                                : mkv  + ((size_t)n * 64 +  0) * S;
    const float* V = (att == 0) ? hqkv + ((size_t)n * 96 + 64) * S
                                : mkv  + ((size_t)n * 64 + 32) * S;
    float* Out = Z2 + ((size_t)n * 64 + att * 32) * S;

    const float scale = 0.17677669529663687f * 1.4426950408889634f;  // log2e/sqrt(32)
    for (int i = tid; i < 4096; i += 128) {
        int d = i >> 7, q = i & 127;
        Qh[q * 40 + d] = __float2bfloat16(Q[(size_t)d * S + q0 + q] * scale);
    }
    __syncthreads();

    uint32_t qa[2][2][4];
#pragma unroll
    for (int mt = 0; mt < 2; mt++) {
        int r0 = 32 * w + 16 * mt + lq;
#pragma unroll
        for (int ks = 0; ks < 2; ks++) {
            qa[mt][ks][0] = Qsw[r0 * 20 + ks * 8 + lj];
            qa[mt][ks][1] = Qsw[(r0 + 8) * 20 + ks * 8 + lj];
            qa[mt][ks][2] = Qsw[r0 * 20 + ks * 8 + lj + 4];
            qa[mt][ks][3] = Qsw[(r0 + 8) * 20 + ks * 8 + lj + 4];
        }
    }

    float oacc[2][4][4];
#pragma unroll
    for (int mt = 0; mt < 2; mt++)
#pragma unroll
        for (int nt = 0; nt < 4; nt++)
#pragma unroll
            for (int r = 0; r < 4; r++) oacc[mt][nt][r] = 0.f;
    float l_acc[4] = {0.f, 0.f, 0.f, 0.f};

    // ---- prefetch chunk 0 into regs (K bf16, V f16)
    uint32_t kreg[8], vreg[8];
#pragma unroll
    for (int j = 0; j < 8; j++) {
        int idx = j * 128 + tid;
        int k = idx & 63, dp = idx >> 6;
        kreg[j] = packbf(K[(size_t)(2 * dp) * S + k], K[(size_t)(2 * dp + 1) * S + k]);
    }
#pragma unroll
    for (int j = 0; j < 8; j++) {
        int idx = j * 128 + tid;
        int d = idx >> 5, kp = idx & 31;
        float2 v2 = *(const float2*)&V[(size_t)d * S + 2 * kp];
        vreg[j] = packh(v2.x, v2.y);
    }

#pragma unroll 1
    for (int kt = 0; kt < 64; kt++) {
        uint32_t* Kbuf = Kb0 + (kt & 1) * AK_W;
        uint32_t* Vbuf = Vb0 + (kt & 1) * AV_W;
#pragma unroll
        for (int j = 0; j < 8; j++) {
            int idx = j * 128 + tid;
            Kbuf[(idx & 63) * 20 + (idx >> 6)] = kreg[j];
        }
#pragma unroll
        for (int j = 0; j < 8; j++) {
            int idx = j * 128 + tid;
            Vbuf[(idx >> 5) * 35 + (idx & 31)] = vreg[j];
        }
        __syncthreads();

        if (kt < 63) {
            int kb = (kt + 1) * 64;
#pragma unroll
            for (int j = 0; j < 8; j++) {
                int idx = j * 128 + tid;
                int k = idx & 63, dp = idx >> 6;
                kreg[j] = packbf(K[(size_t)(2 * dp) * S + kb + k], K[(size_t)(2 * dp + 1) * S + kb + k]);
            }
#pragma unroll
            for (int j = 0; j < 8; j++) {
                int idx = j * 128 + tid;
                int d = idx >> 5, kp = idx & 31;
                float2 v2 = *(const float2*)&V[(size_t)d * S + kb + 2 * kp];
                vreg[j] = packh(v2.x, v2.y);
            }
        }

        // ---- QK (bf16) + base-2 softmax (f16x2) + P fragments (f16)
        uint32_t p[2][4][4];
        uint32_t rsh[2][2] = {{0u, 0u}, {0u, 0u}};   // f16x2 partial row sums
#pragma unroll
        for (int nn = 0; nn < 8; nn++) {
            float c[2][4];
#pragma unroll
            for (int mt = 0; mt < 2; mt++)
#pragma unroll
                for (int r = 0; r < 4; r++) c[mt][r] = 0.f;
#pragma unroll
            for (int ks = 0; ks < 2; ks++) {
                int bw = (nn * 8 + lq) * 20 + ks * 8 + lj;
                uint32_t b0 = Kbuf[bw], b1 = Kbuf[bw + 4];
                mma16816(c[0], qa[0][ks], b0, b1);
                mma16816(c[1], qa[1][ks], b0, b1);
            }
            int kk = nn >> 1, half = (nn & 1) * 2;
#pragma unroll
            for (int mt = 0; mt < 2; mt++) {
                uint32_t p01 = h2ex2(packh(c[mt][0], c[mt][1]));
                uint32_t p23 = h2ex2(packh(c[mt][2], c[mt][3]));
                rsh[mt][0] = hadd2u(rsh[mt][0], p01);
                rsh[mt][1] = hadd2u(rsh[mt][1], p23);
                p[mt][kk][half + 0] = p01;
                p[mt][kk][half + 1] = p23;
            }
        }
#pragma unroll
        for (int mt = 0; mt < 2; mt++) {
            float2 f0 = __half22float2(*(__half2*)&rsh[mt][0]);
            float2 f1 = __half22float2(*(__half2*)&rsh[mt][1]);
            float r0 = f0.x + f0.y, r1 = f1.x + f1.y;
            r0 += __shfl_xor_sync(0xffffffffu, r0, 1);
            r0 += __shfl_xor_sync(0xffffffffu, r0, 2);
            r1 += __shfl_xor_sync(0xffffffffu, r1, 1);
            r1 += __shfl_xor_sync(0xffffffffu, r1, 2);
            l_acc[mt * 2 + 0] += r0;
            l_acc[mt * 2 + 1] += r1;
        }

        // ---- O += P @ V (f16 MMA)
#pragma unroll
        for (int nt = 0; nt < 4; nt++) {
#pragma unroll
            for (int kk = 0; kk < 4; kk++) {
                int bw = (nt * 8 + lq) * 35 + kk * 8 + lj;
                uint32_t b0 = Vbuf[bw], b1 = Vbuf[bw + 4];
                mma16816h(oacc[0][nt], p[0][kk], b0, b1);
                mma16816h(oacc[1][nt], p[1][kk], b0, b1);
            }
        }
    }

    // ---- epilogue
    __syncthreads();
    float* Osm = (float*)smw;
    float inv[4];
#pragma unroll
    for (int r = 0; r < 4; r++) inv[r] = 1.0f / l_acc[r];
#pragma unroll
    for (int mt = 0; mt < 2; mt++) {
        int r0 = 32 * w + 16 * mt + lq;
#pragma unroll
        for (int nt = 0; nt < 4; nt++) {
            int d0 = nt * 8 + 2 * lj;
            Osm[(d0 + 0) * 130 + r0]     = oacc[mt][nt][0] * inv[mt * 2];
            Osm[(d0 + 1) * 130 + r0]     = oacc[mt][nt][1] * inv[mt * 2];
            Osm[(d0 + 0) * 130 + r0 + 8] = oacc[mt][nt][2] * inv[mt * 2 + 1];
            Osm[(d0 + 1) * 130 + r0 + 8] = oacc[mt][nt][3] * inv[mt * 2 + 1];
        }
    }
    __syncthreads();
    for (int i = tid; i < 4096; i += 128) {
        int d = i >> 7, q = i & 127;
        Out[(size_t)d * S + q0 + q] = Osm[d * 130 + q];
    }
}

// ---------------- 3x3 conv implicit GEMM (round-8 version, kept) ----------------
__global__ __launch_bounds__(256)
void conv_tc_kernel(const float* __restrict__ Zin, const float* __restrict__ hin,
                    const float* __restrict__ Wo, const float* __restrict__ bo,
                    float* __restrict__ out) {
    __shared__ uint32_t patchF[16 * 332];
    __shared__ uint4 Wfrag[18 * 2 * 32];

    int tid = threadIdx.x;
    int w = tid >> 5, lane = tid & 31;
    int lq = lane >> 2, l4 = lane & 3;
    int n = blockIdx.z, cog = blockIdx.y, tile = blockIdx.x;
    int ty0 = (tile >> 2) * 16, tx0 = (tile & 3) * 16;

    int pos0 = tid;
    int yy0 = pos0 / 18 + ty0 - 1, xx0 = pos0 % 18 + tx0 - 1;
    bool va0 = (yy0 >= 0 && yy0 < HH && xx0 >= 0 && xx0 < WW);
    int g0 = yy0 * WW + xx0;
    int pos1 = tid + 256;
    bool has1 = pos1 < 324;
    int yy1 = pos1 / 18 + ty0 - 1, xx1 = pos1 % 18 + tx0 - 1;
    bool va1 = has1 && (yy1 >= 0 && yy1 < HH && xx1 >= 0 && xx1 < WW);
    int g1 = yy1 * WW + xx1;

    const uint32_t* rowA = patchF + l4 * 332;
    const uint32_t* rowB = patchF + (8 + l4) * 332;
    int bbase[4];
#pragma unroll
    for (int nt = 0; nt < 4; nt++)
        bbase[nt] = (2 * w + (nt >> 1)) * 18 + (nt & 1) * 8 + lq;

    float oacc[2][4][4];
#pragma unroll
    for (int mt = 0; mt < 2; mt++)
#pragma unroll
        for (int nt = 0; nt < 4; nt++)
#pragma unroll
            for (int r = 0; r < 4; r++) oacc[mt][nt][r] = 0.f;

#pragma unroll 1
    for (int cig = 0; cig < 6; cig++) {
        const float* base = (cig < 2)
            ? Zin + ((size_t)n * 32 + cig * 16) * S
            : hin + ((size_t)n * 64 + (cig * 16 - 32)) * S;
        __syncthreads();
#pragma unroll
        for (int ci = 0; ci < 16; ci++)
            patchF[ci * 332 + pos0] = va0 ? f2tf32(base[(size_t)ci * S + g0]) : 0u;
        if (has1) {
#pragma unroll
            for (int ci = 0; ci < 16; ci++)
                patchF[ci * 332 + pos1] = va1 ? f2tf32(base[(size_t)ci * S + g1]) : 0u;
        }
        for (int i = tid; i < 1152; i += 256) {
            int ln = i & 31, mtc = i >> 5;
            int mt = mtc & 1, chunk = mtc >> 1;
            int khkw = chunk >> 1, c8 = chunk & 1;
            int ciL = c8 * 8 + (ln & 3);
            int co0 = mt * 16 + (ln >> 2);
            const float* wp = Wo + (((size_t)cog * 32 + co0) * 96 + cig * 16 + ciL) * 9 + khkw;
            Wfrag[i] = make_uint4(f2tf32(wp[0]), f2tf32(wp[8 * 864]),
                                  f2tf32(wp[36]), f2tf32(wp[8 * 864 + 36]));
        }
        __syncthreads();

#pragma unroll
        for (int khkw = 0; khkw < 9; khkw++) {
            int kh = khkw / 3, kw = khkw % 3;
#pragma unroll
            for (int c8 = 0; c8 < 2; c8++) {
                int chunk = khkw * 2 + c8;
                uint4 a0 = Wfrag[(chunk * 2 + 0) * 32 + lane];
                uint4 a1 = Wfrag[(chunk * 2 + 1) * 32 + lane];
                const uint32_t* rr = c8 ? rowB : rowA;
#pragma unroll
                for (int nt = 0; nt < 4; nt++) {
                    int off = bbase[nt] + kh * 18 + kw;
                    uint32_t b0 = rr[off];
                    uint32_t b1 = rr[4 * 332 + off];
                    mma1688t(oacc[0][nt], (const uint32_t*)&a0, b0, b1);
                    mma1688t(oacc[1][nt], (const uint32_t*)&a1, b0, b1);
                }
            }
        }
    }

#pragma unroll
    for (int mt = 0; mt < 2; mt++) {
        int coA = cog * 32 + mt * 16 + lq;
        int coB = coA + 8;
        float bA = bo[coA], bB = bo[coB];
        size_t baseA = ((size_t)n * 192 + coA) * S;
        size_t baseB = ((size_t)n * 192 + coB) * S;
#pragma unroll
        for (int nt = 0; nt < 4; nt++) {
            int y = ty0 + 2 * w + (nt >> 1);
            int x = tx0 + (nt & 1) * 8 + 2 * l4;
            *(float2*)&out[baseA + y * WW + x] = make_float2(oacc[mt][nt][0] + bA, oacc[mt][nt][1] + bA);
            *(float2*)&out[baseB + y * WW + x] = make_float2(oacc[mt][nt][2] + bB, oacc[mt][nt][3] + bB);
        }
    }
}

// ---------------- gates (float4) ----------------
__global__ __launch_bounds__(256)
void gates_kernel(const float* __restrict__ conv, const float* __restrict__ m,
                  float* __restrict__ out) {
    int idx4 = blockIdx.x * 256 + threadIdx.x;
    int n = idx4 >> 16;
    int rem = (idx4 & 65535) * 4;
    size_t base = (size_t)n * 192 * S;
    float4 iv = *(const float4*)&conv[base + rem];
    float4 gv = *(const float4*)&conv[base + 64 * S + rem];
    float4 ov = *(const float4*)&conv[base + 128 * S + rem];
    float4 mi = *(const float4*)&m[(size_t)n * 64 * S + rem];
    float4 hn, mn;
    {
        float si = 1.0f / (1.0f + __expf(-iv.x)), gg = tanhf(gv.x), so = 1.0f / (1.0f + __expf(-ov.x));
        mn.x = si * gg + (1.0f - si) * mi.x; hn.x = so * mn.x;
        si = 1.0f / (1.0f + __expf(-iv.y)); gg = tanhf(gv.y); so = 1.0f / (1.0f + __expf(-ov.y));
        mn.y = si * gg + (1.0f - si) * mi.y; hn.y = so * mn.y;
        si = 1.0f / (1.0f + __expf(-iv.z)); gg = tanhf(gv.z); so = 1.0f / (1.0f + __expf(-ov.z));
        mn.z = si * gg + (1.0f - si) * mi.z; hn.z = so * mn.z;
        si = 1.0f / (1.0f + __expf(-iv.w)); gg = tanhf(gv.w); so = 1.0f / (1.0f + __expf(-ov.w));
        mn.w = si * gg + (1.0f - si) * mi.w; hn.w = so * mn.w;
    }
    size_t oidx = (size_t)n * 64 * S + rem;
    *(float4*)&out[oidx] = hn;
    *(float4*)&out[1048576 + oidx] = mn;
}

// ---------------- launch ----------------
extern "C" void kernel_launch(void* const* d_in, const int* in_sizes, int n_in,
                              void* d_out, int out_size) {
    const float* h  = (const float*)d_in[0];
    const float* m  = (const float*)d_in[1];
    const float* Wh = (const float*)d_in[2];
    const float* bh = (const float*)d_in[3];
    const float* Wm = (const float*)d_in[4];
    const float* bm = (const float*)d_in[5];
    const float* Wz = (const float*)d_in[6];
    const float* bz = (const float*)d_in[7];
    const float* Wo = (const float*)d_in[8];
    const float* bo = (const float*)d_in[9];
    float* out = (float*)d_out;

    float *pHqkv, *pMkv, *pZ2, *pZp, *pConv;
    cudaGetSymbolAddress((void**)&pHqkv, g_hqkv);
    cudaGetSymbolAddress((void**)&pMkv,  g_mkv);
    cudaGetSymbolAddress((void**)&pZ2,   g_Z2);
    cudaGetSymbolAddress((void**)&pZp,   g_Zp);
    cudaGetSymbolAddress((void**)&pConv, g_conv);

    projhm_kernel<<<dim3(32, 5, 4), 128>>>(h, Wh, bh, pHqkv, m, Wm, bm, pMkv);
    attn_mma_kernel<<<dim3(32, 2, 4), 128>>>(pHqkv, pMkv, pZ2);
    projz_kernel<<<dim3(32, 1, 4), 128>>>(pZ2, Wz, bz, pZp);
    conv_tc_kernel<<<dim3(16, 6, 4), 256>>>(pZp, h, Wo, bo, pConv);
    gates_kernel<<<1024, 256>>>(pConv, m, out);
}